// round 12
// baseline (speedup 1.0000x reference)
#include <cuda_runtime.h>
#include <cuda_bf16.h>

// HierarchicalSoftmax fused kernel, round 11.
// Base = round-8 winner (TPB=128, 16B loads, batch forced live by __syncwarp,
// smem-transposed epilogue). Delta: TWO samples per warp, software-pipelined:
// sample1's W batch is issued before sample0's epilogue, so the epilogue hides
// sample1's memory latency -> one exposed DRAM latency per two samples.
// Bias values for both samples prefetched with the first batch.
//
// Inputs (metadata order):
//   d_in[0]: embeddings float32 [B, E]   (B=16384, E=128)
//   d_in[1]: word_idx   int32   [B]
//   d_in[2]: W          float32 [V-1, E] (V=131072)
//   d_in[3]: b          float32 [V-1]
// Output: float32 scalar = mean over B of sum over 17 path nodes of BCE.

#define HS_D 17
#define TPB  128
#define WPB  4
#define MAX_BLOCKS 8192
#define NSLOT 9             // slots per half; 9*2 = 18 >= 17 nodes (1 dup)
#define PSTRIDE 20          // floats per node-slot (16 partials + 4 pad; 80B, 16B-aligned)
#define ROW_U2 32           // 128 floats per row = 32 ulonglong2

typedef unsigned long long u64;

__device__ float        g_hs_partials[MAX_BLOCKS];
__device__ unsigned int g_hs_count = 0;   // self-resetting ticket

__device__ __forceinline__ u64 ffma2(u64 a, u64 b, u64 c)
{
    u64 d;
    asm("fma.rn.f32x2 %0, %1, %2, %3;" : "=l"(d) : "l"(a), "l"(b), "l"(c));
    return d;
}

__global__ __launch_bounds__(TPB, 1)
void hs_fused_kernel(const float*  __restrict__ emb,
                     const int*    __restrict__ word_idx,
                     const float4* __restrict__ W4,
                     const float*  __restrict__ bias,
                     float*        __restrict__ out,
                     int B, int Vm1, float invB)
{
    const int warp  = blockIdx.x * WPB + (threadIdx.x >> 5);
    const int wslot = threadIdx.x >> 5;
    const int lane  = threadIdx.x & 31;
    const int half  = lane >> 4;      // node of the slot-pair this lane serves
    const int hl    = lane & 15;      // lane within the 16-lane half

    __shared__ __align__(16) float spart[WPB][2 * NSLOT * PSTRIDE];

    float warp_sum = 0.0f;

    const int s0 = 2 * warp;
    if (s0 < B) {
        const char* __restrict__ Wb = reinterpret_cast<const char*>(W4);
        const int   s1 = s0 + 1;

        // ---- sample metadata + embeddings for BOTH samples ----
        const unsigned leaf0 = (unsigned)__ldg(&word_idx[s0]) + (unsigned)(Vm1 + 1);
        const unsigned leaf1 = (unsigned)__ldg(&word_idx[s1]) + (unsigned)(Vm1 + 1);

        const ulonglong2* er0 = reinterpret_cast<const ulonglong2*>(emb)
                              + (size_t)s0 * ROW_U2 + hl * 2;
        const ulonglong2 e0A = __ldg(er0);
        const ulonglong2 e0B = __ldg(er0 + 1);
        const ulonglong2* er1 = reinterpret_cast<const ulonglong2*>(emb)
                              + (size_t)s1 * ROW_U2 + hl * 2;
        const ulonglong2 e1A = __ldg(er1);
        const ulonglong2 e1B = __ldg(er1 + 1);

        // Epilogue node for this lane (same depth d for both samples).
        const int d  = (lane < HS_D) ? lane : (HS_D - 1);
        const int n0 = (int)((leaf0 >> (d + 1)) - 1u);
        const int n1 = (int)((leaf1 >> (d + 1)) - 1u);
        // Prefetch both bias values (in flight alongside the W batch).
        const float b0 = __ldg(&bias[n0]);
        const float b1 = __ldg(&bias[n1]);

        const int laneoff = hl * 32 - 512;   // row n starts at ((n+1)<<9) - 512

        // ---- pass 1a: issue sample0's full W batch (MLP = 18) ----
        ulonglong2 wA[NSLOT], wB[NSLOT];
        #pragma unroll
        for (int j = 0; j < NSLOT; ++j) {
            const int slot = 2 * j + half;
            const int idx  = (slot < HS_D) ? slot : (HS_D - 1);
            const size_t off = ((size_t)(leaf0 >> (idx + 1)) << 9) + laneoff;
            const ulonglong2* wr = reinterpret_cast<const ulonglong2*>(Wb + off);
            wA[j] = __ldg(wr);
            wB[j] = __ldg(wr + 1);
        }
        __syncwarp();   // keep all 18 results live: one exposed latency

        // ---- pass 2a: FFMA + STS for sample0 ----
        #pragma unroll
        for (int j = 0; j < NSLOT; ++j) {
            const int slot = 2 * j + half;
            u64 p0 = ffma2(wA[j].x, e0A.x, 0ull);
            u64 p1 = ffma2(wA[j].y, e0A.y, 0ull);
            p0 = ffma2(wB[j].x, e0B.x, p0);
            p1 = ffma2(wB[j].y, e0B.y, p1);
            float p0l, p0h, p1l, p1h;
            asm("mov.b64 {%0,%1}, %2;" : "=f"(p0l), "=f"(p0h) : "l"(p0));
            asm("mov.b64 {%0,%1}, %2;" : "=f"(p1l), "=f"(p1h) : "l"(p1));
            spart[wslot][slot * PSTRIDE + hl] = (p0l + p0h) + (p1l + p1h);
        }

        // ---- pass 1b: issue sample1's W batch NOW (overlaps s0 epilogue) ----
        ulonglong2 vA[NSLOT], vB[NSLOT];
        #pragma unroll
        for (int j = 0; j < NSLOT; ++j) {
            const int slot = 2 * j + half;
            const int idx  = (slot < HS_D) ? slot : (HS_D - 1);
            const size_t off = ((size_t)(leaf1 >> (idx + 1)) << 9) + laneoff;
            const ulonglong2* wr = reinterpret_cast<const ulonglong2*>(Wb + off);
            vA[j] = __ldg(wr);
            vB[j] = __ldg(wr + 1);
        }
        __syncwarp();   // spart writes (s0) visible; v-batch stays live

        // ---- epilogue s0 (runs while sample1's loads are in flight) ----
        {
            const float4* pv = reinterpret_cast<const float4*>(
                                   &spart[wslot][d * PSTRIDE]);
            const float4 a0 = pv[0], a1 = pv[1], a2 = pv[2], a3 = pv[3];
            const float dot = ((a0.x + a0.y) + (a0.z + a0.w))
                            + ((a1.x + a1.y) + (a1.z + a1.w))
                            + ((a2.x + a2.y) + (a2.z + a2.w))
                            + ((a3.x + a3.y) + (a3.z + a3.w));
            const float s = dot + b0;
            const float t = (float)(((leaf0 >> d) & 1u) ^ 1u);
            float bce = fmaxf(s, 0.0f) - s * t + __logf(1.0f + __expf(-fabsf(s)));
            if (lane >= HS_D) bce = 0.0f;
            warp_sum = bce;
        }
        __syncwarp();   // epilogue-s0 LDS done before pass 2b overwrites spart

        // ---- pass 2b: FFMA + STS for sample1 ----
        #pragma unroll
        for (int j = 0; j < NSLOT; ++j) {
            const int slot = 2 * j + half;
            u64 p0 = ffma2(vA[j].x, e1A.x, 0ull);
            u64 p1 = ffma2(vA[j].y, e1A.y, 0ull);
            p0 = ffma2(vB[j].x, e1B.x, p0);
            p1 = ffma2(vB[j].y, e1B.y, p1);
            float p0l, p0h, p1l, p1h;
            asm("mov.b64 {%0,%1}, %2;" : "=f"(p0l), "=f"(p0h) : "l"(p0));
            asm("mov.b64 {%0,%1}, %2;" : "=f"(p1l), "=f"(p1h) : "l"(p1));
            spart[wslot][slot * PSTRIDE + hl] = (p0l + p0h) + (p1l + p1h);
        }
        __syncwarp();

        // ---- epilogue s1 ----
        {
            const float4* pv = reinterpret_cast<const float4*>(
                                   &spart[wslot][d * PSTRIDE]);
            const float4 a0 = pv[0], a1 = pv[1], a2 = pv[2], a3 = pv[3];
            const float dot = ((a0.x + a0.y) + (a0.z + a0.w))
                            + ((a1.x + a1.y) + (a1.z + a1.w))
                            + ((a2.x + a2.y) + (a2.z + a2.w))
                            + ((a3.x + a3.y) + (a3.z + a3.w));
            const float s = dot + b1;
            const float t = (float)(((leaf1 >> d) & 1u) ^ 1u);
            float bce = fmaxf(s, 0.0f) - s * t + __logf(1.0f + __expf(-fabsf(s)));
            if (lane >= HS_D) bce = 0.0f;
            warp_sum += bce;
        }

        // One butterfly for both samples.
        warp_sum += __shfl_xor_sync(0xffffffffu, warp_sum, 16);
        warp_sum += __shfl_xor_sync(0xffffffffu, warp_sum, 8);
        warp_sum += __shfl_xor_sync(0xffffffffu, warp_sum, 4);
        warp_sum += __shfl_xor_sync(0xffffffffu, warp_sum, 2);
        warp_sum += __shfl_xor_sync(0xffffffffu, warp_sum, 1);
    }

    // ---- block reduction + last-block grid reduction (deterministic) ----
    __shared__ float sacc[WPB];
    __shared__ bool  is_last;
    if (lane == 0) sacc[wslot] = warp_sum;
    __syncthreads();
    if (threadIdx.x == 0) {
        float ssum = 0.0f;
        #pragma unroll
        for (int i = 0; i < WPB; ++i) ssum += sacc[i];
        g_hs_partials[blockIdx.x] = ssum;
        __threadfence();
        unsigned tk = atomicInc(&g_hs_count, gridDim.x - 1);
        is_last = (tk == gridDim.x - 1);
    }
    __syncthreads();

    if (is_last) {
        float a = 0.0f;
        for (int i = threadIdx.x; i < (int)gridDim.x; i += TPB)
            a += g_hs_partials[i];
        __shared__ float red[TPB];
        red[threadIdx.x] = a;
        __syncthreads();
        #pragma unroll
        for (int ofs = TPB / 2; ofs > 0; ofs >>= 1) {
            if (threadIdx.x < ofs) red[threadIdx.x] += red[threadIdx.x + ofs];
            __syncthreads();
        }
        if (threadIdx.x == 0) out[0] = red[0] * invB;
    }
}

extern "C" void kernel_launch(void* const* d_in, const int* in_sizes, int n_in,
                              void* d_out, int out_size)
{
    const float*  emb      = (const float*) d_in[0];
    const int*    word_idx = (const int*)   d_in[1];
    const float4* W4       = (const float4*)d_in[2];
    const float*  bias     = (const float*) d_in[3];
    float* out = (float*)d_out;

    const int B   = in_sizes[1];   // 16384
    const int Vm1 = in_sizes[3];   // V-1 = 131071

    const int samples_per_block = 2 * WPB;                  // 8
    int nblocks = (B + samples_per_block - 1) / samples_per_block;  // 2048
    if (nblocks > MAX_BLOCKS) nblocks = MAX_BLOCKS;

    hs_fused_kernel<<<nblocks, TPB>>>(emb, word_idx, W4, bias, out,
                                      B, Vm1, 1.0f / (float)B);
}

// round 13
// speedup vs baseline: 1.2458x; 1.2458x over previous
#include <cuda_runtime.h>
#include <cuda_bf16.h>

// HierarchicalSoftmax fused kernel, round 12.
// Full-warp row loads: ONE LDG.128 covers a whole 512B W row (lane owns
// floats [4l, 4l+4)). The 8 deep rows (depths 0..7, DRAM-tier, ~unique per
// sample) are front-batched in registers; the 9 shallow rows (top-511 nodes,
// L1/L2-hot) are load-used while the deep batch is in flight. Per-lane
// partials go to conflict-free smem slots (stride 36 words); lane d sums node
// d's 32 partials, computes BCE for all 17 nodes in one block, one butterfly,
// deterministic grid reduction.
//
// Inputs (metadata order):
//   d_in[0]: embeddings float32 [B, E]   (B=16384, E=128)
//   d_in[1]: word_idx   int32   [B]
//   d_in[2]: W          float32 [V-1, E] (V=131072)
//   d_in[3]: b          float32 [V-1]
// Output: float32 scalar = mean over B of sum over 17 path nodes of BCE.

#define HS_D   17
#define TPB    128
#define WPB    4
#define MAX_BLOCKS 8192
#define NDEEP  8            // depths 0..7: DRAM-tier rows, register-batched
#define PSTRIDE 36          // words per partial slot (32 + 4 pad) -> conflict-free

typedef unsigned long long u64;

__device__ float        g_hs_partials[MAX_BLOCKS];
__device__ unsigned int g_hs_count = 0;   // self-resetting ticket

__device__ __forceinline__ u64 ffma2(u64 a, u64 b, u64 c)
{
    u64 d;
    asm("fma.rn.f32x2 %0, %1, %2, %3;" : "=l"(d) : "l"(a), "l"(b), "l"(c));
    return d;
}

// per-lane partial of a row: 4 floats (2 packed f32x2) dotted with embedding
__device__ __forceinline__ float dot4(const ulonglong2 w, const ulonglong2 e)
{
    u64 p = ffma2(w.y, e.y, ffma2(w.x, e.x, 0ull));
    float lo, hi;
    asm("mov.b64 {%0,%1}, %2;" : "=f"(lo), "=f"(hi) : "l"(p));
    return lo + hi;
}

__global__ __launch_bounds__(TPB, 1)
void hs_fused_kernel(const float*  __restrict__ emb,
                     const int*    __restrict__ word_idx,
                     const float4* __restrict__ W4,
                     const float*  __restrict__ bias,
                     float*        __restrict__ out,
                     int B, int Vm1, float invB)
{
    const int warp  = blockIdx.x * WPB + (threadIdx.x >> 5);
    const int wslot = threadIdx.x >> 5;
    const int lane  = threadIdx.x & 31;

    __shared__ __align__(16) float spart[WPB][HS_D * PSTRIDE];

    float warp_sum = 0.0f;

    if (warp < B) {
        const char* __restrict__ Wb = reinterpret_cast<const char*>(W4);

        // 1-based leaf heap index: W-node at depth d = (leaf1 >> (d+1)) - 1;
        // direction bit at depth d = ((leaf1 >> d) & 1) ^ 1.
        const unsigned leaf1 = (unsigned)__ldg(&word_idx[warp])
                             + (unsigned)(Vm1 + 1);

        // Lane owns embedding floats [4*lane, 4*lane+4): one 16B load.
        const ulonglong2 e = __ldg(reinterpret_cast<const ulonglong2*>(
            reinterpret_cast<const char*>(emb) + ((size_t)warp << 9) + lane * 16));

        const int laneoff = lane * 16 - 512;   // row n starts at ((n+1)<<9)-512

        // Epilogue metadata + bias prefetch (in flight with the deep batch).
        const int   d  = (lane < HS_D) ? lane : (HS_D - 1);
        const int   nd = (int)((leaf1 >> (d + 1)) - 1u);
        const float bd = __ldg(&bias[nd]);

        // ---- deep batch: depths 0..7, one LDG.128 per whole row ----
        ulonglong2 wd[NDEEP];
        #pragma unroll
        for (int j = 0; j < NDEEP; ++j) {
            const size_t off = ((size_t)(leaf1 >> (j + 1)) << 9) + laneoff;
            wd[j] = __ldg(reinterpret_cast<const ulonglong2*>(Wb + off));
        }

        // ---- shallow rows: depths 8..16, load-use while deep batch flies ----
        #pragma unroll
        for (int j = NDEEP; j < HS_D; ++j) {
            const size_t off = ((size_t)(leaf1 >> (j + 1)) << 9) + laneoff;
            const ulonglong2 ws =
                __ldg(reinterpret_cast<const ulonglong2*>(Wb + off));
            spart[wslot][j * PSTRIDE + lane] = dot4(ws, e);
        }

        // ---- consume the deep batch ----
        #pragma unroll
        for (int j = 0; j < NDEEP; ++j) {
            spart[wslot][j * PSTRIDE + lane] = dot4(wd[j], e);
        }
        __syncwarp();

        // ---- transposed epilogue: lane d sums node d's 32 partials ----
        const float4* pv = reinterpret_cast<const float4*>(
                               &spart[wslot][d * PSTRIDE]);
        const float4 a0 = pv[0], a1 = pv[1], a2 = pv[2], a3 = pv[3];
        const float4 a4 = pv[4], a5 = pv[5], a6 = pv[6], a7 = pv[7];
        const float dot = (((a0.x + a0.y) + (a0.z + a0.w))
                        +  ((a1.x + a1.y) + (a1.z + a1.w)))
                        + (((a2.x + a2.y) + (a2.z + a2.w))
                        +  ((a3.x + a3.y) + (a3.z + a3.w)))
                        + (((a4.x + a4.y) + (a4.z + a4.w))
                        +  ((a5.x + a5.y) + (a5.z + a5.w)))
                        + (((a6.x + a6.y) + (a6.z + a6.w))
                        +  ((a7.x + a7.y) + (a7.z + a7.w)));

        const float s = dot + bd;
        const float t = (float)(((leaf1 >> d) & 1u) ^ 1u);
        float bce = fmaxf(s, 0.0f) - s * t + __logf(1.0f + __expf(-fabsf(s)));
        if (lane >= HS_D) bce = 0.0f;

        // One butterfly for the whole sample.
        bce += __shfl_xor_sync(0xffffffffu, bce, 16);
        bce += __shfl_xor_sync(0xffffffffu, bce, 8);
        bce += __shfl_xor_sync(0xffffffffu, bce, 4);
        bce += __shfl_xor_sync(0xffffffffu, bce, 2);
        bce += __shfl_xor_sync(0xffffffffu, bce, 1);
        warp_sum = bce;
    }

    // ---- block reduction + last-block grid reduction (deterministic) ----
    __shared__ float sacc[WPB];
    __shared__ bool  is_last;
    if (lane == 0) sacc[wslot] = warp_sum;
    __syncthreads();
    if (threadIdx.x == 0) {
        float ssum = 0.0f;
        #pragma unroll
        for (int i = 0; i < WPB; ++i) ssum += sacc[i];
        g_hs_partials[blockIdx.x] = ssum;
        __threadfence();
        unsigned tk = atomicInc(&g_hs_count, gridDim.x - 1);
        is_last = (tk == gridDim.x - 1);
    }
    __syncthreads();

    if (is_last) {
        float a = 0.0f;
        for (int i = threadIdx.x; i < (int)gridDim.x; i += TPB)
            a += g_hs_partials[i];
        __shared__ float red[TPB];
        red[threadIdx.x] = a;
        __syncthreads();
        #pragma unroll
        for (int ofs = TPB / 2; ofs > 0; ofs >>= 1) {
            if (threadIdx.x < ofs) red[threadIdx.x] += red[threadIdx.x + ofs];
            __syncthreads();
        }
        if (threadIdx.x == 0) out[0] = red[0] * invB;
    }
}

extern "C" void kernel_launch(void* const* d_in, const int* in_sizes, int n_in,
                              void* d_out, int out_size)
{
    const float*  emb      = (const float*) d_in[0];
    const int*    word_idx = (const int*)   d_in[1];
    const float4* W4       = (const float4*)d_in[2];
    const float*  bias     = (const float*) d_in[3];
    float* out = (float*)d_out;

    const int B   = in_sizes[1];   // 16384
    const int Vm1 = in_sizes[3];   // V-1 = 131071

    int nblocks = (B + WPB - 1) / WPB;            // 4096
    if (nblocks > MAX_BLOCKS) nblocks = MAX_BLOCKS;

    hs_fused_kernel<<<nblocks, TPB>>>(emb, word_idx, W4, bias, out,
                                      B, Vm1, 1.0f / (float)B);
}

// round 14
// speedup vs baseline: 1.3695x; 1.0992x over previous
#include <cuda_runtime.h>
#include <cuda_bf16.h>

// HierarchicalSoftmax fused kernel, round 13.
// Deep W rows (depths 0..7, DRAM-tier) are staged to shared memory with
// cp.async (LDGSTS) -> the in-flight batch costs ZERO registers, so occupancy
// rises from 20 to ~32 warps/SM while keeping full per-warp MLP. Shallow rows
// (depths 8..16, top-511 nodes, cache-hot) are load-used while the async batch
// flies. Each lane reads back only its own 16B per deep row (self-issued
// cp.async => no cross-lane visibility needed beyond wait_group).
//
// Inputs (metadata order):
//   d_in[0]: embeddings float32 [B, E]   (B=16384, E=128)
//   d_in[1]: word_idx   int32   [B]
//   d_in[2]: W          float32 [V-1, E] (V=131072)
//   d_in[3]: b          float32 [V-1]
// Output: float32 scalar = mean over B of sum over 17 path nodes of BCE.

#define HS_D   17
#define TPB    128
#define WPB    4
#define MAX_BLOCKS 8192
#define NDEEP  8            // depths 0..7: DRAM-tier rows, cp.async-staged
#define PSTRIDE 36          // words per partial slot (32 + 4 pad) -> conflict-free
#define ROWB   512          // bytes per W row

typedef unsigned long long u64;

__device__ float        g_hs_partials[MAX_BLOCKS];
__device__ unsigned int g_hs_count = 0;   // self-resetting ticket

__device__ __forceinline__ u64 ffma2(u64 a, u64 b, u64 c)
{
    u64 d;
    asm("fma.rn.f32x2 %0, %1, %2, %3;" : "=l"(d) : "l"(a), "l"(b), "l"(c));
    return d;
}

// per-lane partial of a row: 4 floats (2 packed f32x2) dotted with embedding
__device__ __forceinline__ float dot4(const ulonglong2 w, const ulonglong2 e)
{
    u64 p = ffma2(w.y, e.y, ffma2(w.x, e.x, 0ull));
    float lo, hi;
    asm("mov.b64 {%0,%1}, %2;" : "=f"(lo), "=f"(hi) : "l"(p));
    return lo + hi;
}

__global__ __launch_bounds__(TPB, 8)
void hs_fused_kernel(const float*  __restrict__ emb,
                     const int*    __restrict__ word_idx,
                     const float4* __restrict__ W4,
                     const float*  __restrict__ bias,
                     float*        __restrict__ out,
                     int B, int Vm1, float invB)
{
    const int warp  = blockIdx.x * WPB + (threadIdx.x >> 5);
    const int wslot = threadIdx.x >> 5;
    const int lane  = threadIdx.x & 31;

    // cp.async staging for deep rows + transposed partial slots
    __shared__ __align__(16) char  sdeep[WPB][NDEEP * ROWB];
    __shared__ __align__(16) float spart[WPB][HS_D * PSTRIDE];

    float warp_sum = 0.0f;

    if (warp < B) {
        const char* __restrict__ Wb = reinterpret_cast<const char*>(W4);

        // 1-based leaf heap index: W-node at depth d = (leaf1 >> (d+1)) - 1;
        // direction bit at depth d = ((leaf1 >> d) & 1) ^ 1.
        const unsigned leaf1 = (unsigned)__ldg(&word_idx[warp])
                             + (unsigned)(Vm1 + 1);

        const int laneoff = lane * 16 - 512;   // row n starts at ((n+1)<<9)-512

        // ---- stage the 8 deep rows to smem with cp.async (no reg cost) ----
        const unsigned sd_base = (unsigned)__cvta_generic_to_shared(
                                     &sdeep[wslot][0]) + (unsigned)(lane * 16);
        #pragma unroll
        for (int j = 0; j < NDEEP; ++j) {
            const char* gsrc = Wb + (((size_t)(leaf1 >> (j + 1)) << 9) + laneoff);
            asm volatile("cp.async.cg.shared.global [%0], [%1], 16;"
                         :: "r"(sd_base + j * ROWB), "l"(gsrc) : "memory");
        }
        asm volatile("cp.async.commit_group;" ::: "memory");

        // Lane owns embedding floats [4*lane, 4*lane+4): one 16B load.
        const ulonglong2 e = __ldg(reinterpret_cast<const ulonglong2*>(
            reinterpret_cast<const char*>(emb) + ((size_t)warp << 9) + lane * 16));

        // Epilogue metadata + bias prefetch (overlaps the async batch).
        const int   d  = (lane < HS_D) ? lane : (HS_D - 1);
        const int   nd = (int)((leaf1 >> (d + 1)) - 1u);
        const float bd = __ldg(&bias[nd]);

        // ---- shallow rows (depths 8..16, cache-hot): load-use overlap ----
        #pragma unroll
        for (int j = NDEEP; j < HS_D; ++j) {
            const size_t off = ((size_t)(leaf1 >> (j + 1)) << 9) + laneoff;
            const ulonglong2 ws =
                __ldg(reinterpret_cast<const ulonglong2*>(Wb + off));
            spart[wslot][j * PSTRIDE + lane] = dot4(ws, e);
        }

        // ---- wait for the deep batch, consume from smem ----
        asm volatile("cp.async.wait_group 0;" ::: "memory");
        #pragma unroll
        for (int j = 0; j < NDEEP; ++j) {
            const ulonglong2 wdj = *reinterpret_cast<const ulonglong2*>(
                &sdeep[wslot][j * ROWB + lane * 16]);
            spart[wslot][j * PSTRIDE + lane] = dot4(wdj, e);
        }
        __syncwarp();

        // ---- transposed epilogue: lane d sums node d's 32 partials ----
        const float4* pv = reinterpret_cast<const float4*>(
                               &spart[wslot][d * PSTRIDE]);
        const float4 a0 = pv[0], a1 = pv[1], a2 = pv[2], a3 = pv[3];
        const float4 a4 = pv[4], a5 = pv[5], a6 = pv[6], a7 = pv[7];
        const float dot = (((a0.x + a0.y) + (a0.z + a0.w))
                        +  ((a1.x + a1.y) + (a1.z + a1.w)))
                        + (((a2.x + a2.y) + (a2.z + a2.w))
                        +  ((a3.x + a3.y) + (a3.z + a3.w)))
                        + (((a4.x + a4.y) + (a4.z + a4.w))
                        +  ((a5.x + a5.y) + (a5.z + a5.w)))
                        + (((a6.x + a6.y) + (a6.z + a6.w))
                        +  ((a7.x + a7.y) + (a7.z + a7.w)));

        const float s = dot + bd;
        const float t = (float)(((leaf1 >> d) & 1u) ^ 1u);
        float bce = fmaxf(s, 0.0f) - s * t + __logf(1.0f + __expf(-fabsf(s)));
        if (lane >= HS_D) bce = 0.0f;

        // One butterfly for the whole sample.
        bce += __shfl_xor_sync(0xffffffffu, bce, 16);
        bce += __shfl_xor_sync(0xffffffffu, bce, 8);
        bce += __shfl_xor_sync(0xffffffffu, bce, 4);
        bce += __shfl_xor_sync(0xffffffffu, bce, 2);
        bce += __shfl_xor_sync(0xffffffffu, bce, 1);
        warp_sum = bce;
    }

    // ---- block reduction + last-block grid reduction (deterministic) ----
    __shared__ float sacc[WPB];
    __shared__ bool  is_last;
    if (lane == 0) sacc[wslot] = warp_sum;
    __syncthreads();
    if (threadIdx.x == 0) {
        float ssum = 0.0f;
        #pragma unroll
        for (int i = 0; i < WPB; ++i) ssum += sacc[i];
        g_hs_partials[blockIdx.x] = ssum;
        __threadfence();
        unsigned tk = atomicInc(&g_hs_count, gridDim.x - 1);
        is_last = (tk == gridDim.x - 1);
    }
    __syncthreads();

    if (is_last) {
        float a = 0.0f;
        for (int i = threadIdx.x; i < (int)gridDim.x; i += TPB)
            a += g_hs_partials[i];
        __shared__ float red[TPB];
        red[threadIdx.x] = a;
        __syncthreads();
        #pragma unroll
        for (int ofs = TPB / 2; ofs > 0; ofs >>= 1) {
            if (threadIdx.x < ofs) red[threadIdx.x] += red[threadIdx.x + ofs];
            __syncthreads();
        }
        if (threadIdx.x == 0) out[0] = red[0] * invB;
    }
}

extern "C" void kernel_launch(void* const* d_in, const int* in_sizes, int n_in,
                              void* d_out, int out_size)
{
    const float*  emb      = (const float*) d_in[0];
    const int*    word_idx = (const int*)   d_in[1];
    const float4* W4       = (const float4*)d_in[2];
    const float*  bias     = (const float*) d_in[3];
    float* out = (float*)d_out;

    const int B   = in_sizes[1];   // 16384
    const int Vm1 = in_sizes[3];   // V-1 = 131071

    int nblocks = (B + WPB - 1) / WPB;            // 4096
    if (nblocks > MAX_BLOCKS) nblocks = MAX_BLOCKS;

    hs_fused_kernel<<<nblocks, TPB>>>(emb, word_idx, W4, bias, out,
                                      B, Vm1, 1.0f / (float)B);
}

// round 15
// speedup vs baseline: 1.5152x; 1.1064x over previous
#include <cuda_runtime.h>
#include <cuda_bf16.h>

// HierarchicalSoftmax fused kernel, round 14.
// Base = round-13 (cp.async-staged deep rows, zero-register batch). Delta:
// the deep partial slots are ALIASED into the staging buffer (slot j lives
// inside row j's 512B area at byte 528j, same conflict-free bank phase as
// stride-36), cutting smem/block ~26.4KB -> ~21.7KB, so 9 blocks (36 warps)
// fit per SM instead of 8.
//
// Inputs (metadata order):
//   d_in[0]: embeddings float32 [B, E]   (B=16384, E=128)
//   d_in[1]: word_idx   int32   [B]
//   d_in[2]: W          float32 [V-1, E] (V=131072)
//   d_in[3]: b          float32 [V-1]
// Output: float32 scalar = mean over B of sum over 17 path nodes of BCE.

#define HS_D   17
#define TPB    128
#define WPB    4
#define MAX_BLOCKS 8192
#define NDEEP  8            // depths 0..7: DRAM-tier rows, cp.async-staged
#define NSHAL  (HS_D - NDEEP)   // 9 shallow (cache-hot) rows
#define ROWB   512          // bytes per W row
#define DSLOT  528          // byte offset of deep slot j inside sdeep (528*j)
#define SSTRIDE 36          // words per shallow slot (32 + 4 pad)

typedef unsigned long long u64;

__device__ float        g_hs_partials[MAX_BLOCKS];
__device__ unsigned int g_hs_count = 0;   // self-resetting ticket

__device__ __forceinline__ u64 ffma2(u64 a, u64 b, u64 c)
{
    u64 d;
    asm("fma.rn.f32x2 %0, %1, %2, %3;" : "=l"(d) : "l"(a), "l"(b), "l"(c));
    return d;
}

// per-lane partial of a row: 4 floats (2 packed f32x2) dotted with embedding
__device__ __forceinline__ float dot4(const ulonglong2 w, const ulonglong2 e)
{
    u64 p = ffma2(w.y, e.y, ffma2(w.x, e.x, 0ull));
    float lo, hi;
    asm("mov.b64 {%0,%1}, %2;" : "=f"(lo), "=f"(hi) : "l"(p));
    return lo + hi;
}

// sum 36-byte-phase slot: 8 float4 reads (conflict-free), pairwise tree sum
__device__ __forceinline__ float sum_slot(const float* base)
{
    const float4* pv = reinterpret_cast<const float4*>(base);
    const float4 a0 = pv[0], a1 = pv[1], a2 = pv[2], a3 = pv[3];
    const float4 a4 = pv[4], a5 = pv[5], a6 = pv[6], a7 = pv[7];
    return (((a0.x + a0.y) + (a0.z + a0.w))
         +  ((a1.x + a1.y) + (a1.z + a1.w)))
         + (((a2.x + a2.y) + (a2.z + a2.w))
         +  ((a3.x + a3.y) + (a3.z + a3.w)))
         + (((a4.x + a4.y) + (a4.z + a4.w))
         +  ((a5.x + a5.y) + (a5.z + a5.w)))
         + (((a6.x + a6.y) + (a6.z + a6.w))
         +  ((a7.x + a7.y) + (a7.z + a7.w)));
}

__global__ __launch_bounds__(TPB, 9)
void hs_fused_kernel(const float*  __restrict__ emb,
                     const int*    __restrict__ word_idx,
                     const float4* __restrict__ W4,
                     const float*  __restrict__ bias,
                     float*        __restrict__ out,
                     int B, int Vm1, float invB)
{
    const int warp  = blockIdx.x * WPB + (threadIdx.x >> 5);
    const int wslot = threadIdx.x >> 5;
    const int lane  = threadIdx.x & 31;

    // Deep staging (8 x 512B); deep partial slot j aliased at byte 528*j,
    // which sits wholly inside row j's area and is written only after row j
    // has been consumed. Shallow slots are a separate small array.
    __shared__ __align__(16) char  sdeep[WPB][NDEEP * ROWB];
    __shared__ __align__(16) float sshal[WPB][NSHAL * SSTRIDE];

    float warp_sum = 0.0f;

    if (warp < B) {
        const char* __restrict__ Wb = reinterpret_cast<const char*>(W4);

        // 1-based leaf heap index: W-node at depth d = (leaf1 >> (d+1)) - 1;
        // direction bit at depth d = ((leaf1 >> d) & 1) ^ 1.
        const unsigned leaf1 = (unsigned)__ldg(&word_idx[warp])
                             + (unsigned)(Vm1 + 1);

        const int laneoff = lane * 16 - 512;   // row n starts at ((n+1)<<9)-512

        // ---- stage the 8 deep rows to smem with cp.async (no reg cost) ----
        const unsigned sd_base = (unsigned)__cvta_generic_to_shared(
                                     &sdeep[wslot][0]);
        #pragma unroll
        for (int j = 0; j < NDEEP; ++j) {
            const char* gsrc = Wb + (((size_t)(leaf1 >> (j + 1)) << 9) + laneoff);
            asm volatile("cp.async.cg.shared.global [%0], [%1], 16;"
                         :: "r"(sd_base + j * ROWB + lane * 16), "l"(gsrc)
                         : "memory");
        }
        asm volatile("cp.async.commit_group;" ::: "memory");

        // Lane owns embedding floats [4*lane, 4*lane+4): one 16B load.
        const ulonglong2 e = __ldg(reinterpret_cast<const ulonglong2*>(
            reinterpret_cast<const char*>(emb) + ((size_t)warp << 9) + lane * 16));

        // Epilogue metadata + bias prefetch (overlaps the async batch).
        const int   d  = (lane < HS_D) ? lane : (HS_D - 1);
        const int   nd = (int)((leaf1 >> (d + 1)) - 1u);
        const float bd = __ldg(&bias[nd]);

        // ---- shallow rows (depths 8..16, cache-hot): load-use overlap ----
        #pragma unroll
        for (int j = NDEEP; j < HS_D; ++j) {
            const size_t off = ((size_t)(leaf1 >> (j + 1)) << 9) + laneoff;
            const ulonglong2 ws =
                __ldg(reinterpret_cast<const ulonglong2*>(Wb + off));
            sshal[wslot][(j - NDEEP) * SSTRIDE + lane] = dot4(ws, e);
        }

        // ---- wait for the deep batch, consume + write aliased slots ----
        asm volatile("cp.async.wait_group 0;" ::: "memory");
        #pragma unroll
        for (int j = 0; j < NDEEP; ++j) {
            // read row j (LDS.128, conflict-free) ...
            const ulonglong2 wdj = *reinterpret_cast<const ulonglong2*>(
                &sdeep[wslot][j * ROWB + lane * 16]);
            const float pj = dot4(wdj, e);
            // ... then write slot j inside row j's (now-consumed) area
            *reinterpret_cast<float*>(
                &sdeep[wslot][j * DSLOT + lane * 4]) = pj;
        }
        __syncwarp();

        // ---- transposed epilogue: lane d sums node d's 32 partials ----
        const float* slot_base = (d < NDEEP)
            ? reinterpret_cast<const float*>(&sdeep[wslot][d * DSLOT])
            : &sshal[wslot][(d - NDEEP) * SSTRIDE];
        const float dot = sum_slot(slot_base);

        const float s = dot + bd;
        const float t = (float)(((leaf1 >> d) & 1u) ^ 1u);
        float bce = fmaxf(s, 0.0f) - s * t + __logf(1.0f + __expf(-fabsf(s)));
        if (lane >= HS_D) bce = 0.0f;

        // One butterfly for the whole sample.
        bce += __shfl_xor_sync(0xffffffffu, bce, 16);
        bce += __shfl_xor_sync(0xffffffffu, bce, 8);
        bce += __shfl_xor_sync(0xffffffffu, bce, 4);
        bce += __shfl_xor_sync(0xffffffffu, bce, 2);
        bce += __shfl_xor_sync(0xffffffffu, bce, 1);
        warp_sum = bce;
    }

    // ---- block reduction + last-block grid reduction (deterministic) ----
    __shared__ float sacc[WPB];
    __shared__ bool  is_last;
    if (lane == 0) sacc[wslot] = warp_sum;
    __syncthreads();
    if (threadIdx.x == 0) {
        float ssum = 0.0f;
        #pragma unroll
        for (int i = 0; i < WPB; ++i) ssum += sacc[i];
        g_hs_partials[blockIdx.x] = ssum;
        __threadfence();
        unsigned tk = atomicInc(&g_hs_count, gridDim.x - 1);
        is_last = (tk == gridDim.x - 1);
    }
    __syncthreads();

    if (is_last) {
        float a = 0.0f;
        for (int i = threadIdx.x; i < (int)gridDim.x; i += TPB)
            a += g_hs_partials[i];
        __shared__ float red[TPB];
        red[threadIdx.x] = a;
        __syncthreads();
        #pragma unroll
        for (int ofs = TPB / 2; ofs > 0; ofs >>= 1) {
            if (threadIdx.x < ofs) red[threadIdx.x] += red[threadIdx.x + ofs];
            __syncthreads();
        }
        if (threadIdx.x == 0) out[0] = red[0] * invB;
    }
}

extern "C" void kernel_launch(void* const* d_in, const int* in_sizes, int n_in,
                              void* d_out, int out_size)
{
    const float*  emb      = (const float*) d_in[0];
    const int*    word_idx = (const int*)   d_in[1];
    const float4* W4       = (const float4*)d_in[2];
    const float*  bias     = (const float*) d_in[3];
    float* out = (float*)d_out;

    const int B   = in_sizes[1];   // 16384
    const int Vm1 = in_sizes[3];   // V-1 = 131071

    int nblocks = (B + WPB - 1) / WPB;            // 4096
    if (nblocks > MAX_BLOCKS) nblocks = MAX_BLOCKS;

    hs_fused_kernel<<<nblocks, TPB>>>(emb, word_idx, W4, bias, out,
                                      B, Vm1, 1.0f / (float)B);
}